// round 14
// baseline (speedup 1.0000x reference)
#include <cuda_runtime.h>
#include <cuda_fp16.h>
#include <cstddef>

#define N_NODES 100000
#define N_EDGES 3200000
#define F_IN    256
#define F_OUT   64
#define NF      (N_NODES * F_OUT)
#define SCAN_BLK 1024
#define NB_SCAN  ((N_NODES + SCAN_BLK - 1) / SCAN_BLK)   // 98

// Scratch (device globals; allocation-free).
__device__ float    g_s0[NF];
__device__ __half   g_s0h[NF];            // fp16 s0 (gather source)
__device__ __half   g_acch[6][NF];        // fp16 channels: hA,hA2,hA3,hs1,hs2,hs3
__device__ int      g_cnt[4][N_NODES];
__device__ int      g_rowptr[4][N_NODES + 1];
__device__ unsigned g_rank[4][N_EDGES];   // packed (row<<15)|rank
__device__ int2     g_edges[4][N_EDGES];  // (col, val-as-int), dest-sorted
__device__ int      g_bsum[4][NB_SCAN + 1];
__device__ int      g_bsumx[4][NB_SCAN + 1];

// ---------------------------------------------------------------------------
// GEMM: s0[N,64] = x[N,256] @ W[256,64], fp32; also emits fp16 copy.
// ---------------------------------------------------------------------------
__global__ void gemm64(const float* __restrict__ x, const float* __restrict__ W,
                       float* __restrict__ out, __half* __restrict__ outh)
{
    __shared__ float xs[32][64];
    __shared__ float ws[32][64];

    const int tid = threadIdx.x;       // 0..127
    const int tx  = tid & 7;
    const int ty  = tid >> 3;
    const int r0  = blockIdx.x * 64;

    float4 acc0[4] = {};
    float4 acc1[4] = {};

    for (int k0 = 0; k0 < F_IN; k0 += 32) {
        #pragma unroll
        for (int it = 0; it < 4; it++) {
            int li  = it * 128 + tid;
            int row = li >> 3;
            int kq  = li & 7;
            float4 v = make_float4(0.f, 0.f, 0.f, 0.f);
            int gr = r0 + row;
            if (gr < N_NODES)
                v = *(const float4*)(x + (size_t)gr * F_IN + k0 + kq * 4);
            xs[kq * 4 + 0][row] = v.x;
            xs[kq * 4 + 1][row] = v.y;
            xs[kq * 4 + 2][row] = v.z;
            xs[kq * 4 + 3][row] = v.w;
        }
        #pragma unroll
        for (int it = 0; it < 4; it++) {
            int li = it * 128 + tid;
            int kk = li >> 4;
            int cq = li & 15;
            *(float4*)&ws[kk][cq * 4] =
                *(const float4*)(W + (size_t)(k0 + kk) * F_OUT + cq * 4);
        }
        __syncthreads();

        #pragma unroll
        for (int kk = 0; kk < 32; kk++) {
            float4 av = *(const float4*)&xs[kk][ty * 4];
            float4 b0 = *(const float4*)&ws[kk][tx * 4];
            float4 b1 = *(const float4*)&ws[kk][tx * 4 + 32];
            float a4[4] = {av.x, av.y, av.z, av.w};
            #pragma unroll
            for (int j = 0; j < 4; j++) {
                acc0[j].x = fmaf(a4[j], b0.x, acc0[j].x);
                acc0[j].y = fmaf(a4[j], b0.y, acc0[j].y);
                acc0[j].z = fmaf(a4[j], b0.z, acc0[j].z);
                acc0[j].w = fmaf(a4[j], b0.w, acc0[j].w);
                acc1[j].x = fmaf(a4[j], b1.x, acc1[j].x);
                acc1[j].y = fmaf(a4[j], b1.y, acc1[j].y);
                acc1[j].z = fmaf(a4[j], b1.z, acc1[j].z);
                acc1[j].w = fmaf(a4[j], b1.w, acc1[j].w);
            }
        }
        __syncthreads();
    }

    #pragma unroll
    for (int j = 0; j < 4; j++) {
        int gr = r0 + ty * 4 + j;
        if (gr < N_NODES) {
            *(float4*)(out + (size_t)gr * F_OUT + tx * 4)      = acc0[j];
            *(float4*)(out + (size_t)gr * F_OUT + tx * 4 + 32) = acc1[j];
            __half2* hp = (__half2*)(outh + (size_t)gr * F_OUT);
            hp[tx * 2]      = __floats2half2_rn(acc0[j].x, acc0[j].y);
            hp[tx * 2 + 1]  = __floats2half2_rn(acc0[j].z, acc0[j].w);
            hp[tx * 2 + 16] = __floats2half2_rn(acc1[j].x, acc1[j].y);
            hp[tx * 2 + 17] = __floats2half2_rn(acc1[j].z, acc1[j].w);
        }
    }
}

// ---------------------------------------------------------------------------
// CSR build (fused across 4 operators via blockIdx.y)
// ---------------------------------------------------------------------------
__global__ void hist_rank(const int* __restrict__ i0, const int* __restrict__ i1,
                          const int* __restrict__ i2, const int* __restrict__ i3,
                          int* __restrict__ cnt, unsigned* __restrict__ rank)
{
    const int op = blockIdx.y;
    const int* idx = (op == 0) ? i0 : (op == 1) ? i1 : (op == 2) ? i2 : i3;
    int e = (blockIdx.x * blockDim.x + threadIdx.x) * 2;
    if (e + 1 < N_EDGES) {
        int2 rr = *(const int2*)(idx + e);
        unsigned k0 = atomicAdd(&cnt[op * N_NODES + rr.x], 1);
        unsigned k1 = atomicAdd(&cnt[op * N_NODES + rr.y], 1);
        uint2 pk = make_uint2(((unsigned)rr.x << 15) | k0,
                              ((unsigned)rr.y << 15) | k1);
        *(uint2*)(rank + (size_t)op * N_EDGES + e) = pk;
    }
}

__global__ void scan_blocks(const int* __restrict__ cnt, int* __restrict__ excl,
                            int* __restrict__ bsum)
{
    __shared__ int sh[256];
    const int op = blockIdx.y;
    const int t = threadIdx.x;
    const int base = blockIdx.x * SCAN_BLK + t * 4;
    const int* c = cnt + op * N_NODES;
    int* ex = excl + op * (N_NODES + 1);

    int v[4];
    #pragma unroll
    for (int i = 0; i < 4; i++)
        v[i] = (base + i < N_NODES) ? c[base + i] : 0;
    int s = v[0] + v[1] + v[2] + v[3];
    sh[t] = s;
    __syncthreads();
    #pragma unroll
    for (int off = 1; off < 256; off <<= 1) {
        int x = (t >= off) ? sh[t - off] : 0;
        __syncthreads();
        sh[t] += x;
        __syncthreads();
    }
    int run = sh[t] - s;
    #pragma unroll
    for (int i = 0; i < 4; i++) {
        if (base + i < N_NODES) ex[base + i] = run;
        run += v[i];
    }
    if (t == 255) bsum[op * (NB_SCAN + 1) + blockIdx.x] = sh[255];
}

__global__ void scan_bsums(const int* __restrict__ bsum, int* __restrict__ bsumx)
{
    const int op   = threadIdx.x >> 5;
    const int lane = threadIdx.x & 31;
    const int* b = bsum  + op * (NB_SCAN + 1);
    int*      bx = bsumx + op * (NB_SCAN + 1);
    int carry = 0;
    #pragma unroll
    for (int c = 0; c < (NB_SCAN + 31) / 32; c++) {
        int i = c * 32 + lane;
        int v = (i < NB_SCAN) ? b[i] : 0;
        int s = v;
        #pragma unroll
        for (int off = 1; off < 32; off <<= 1) {
            int t = __shfl_up_sync(0xffffffffu, s, off);
            if (lane >= off) s += t;
        }
        if (i < NB_SCAN) bx[i] = carry + s - v;
        carry += __shfl_sync(0xffffffffu, s, 31);
    }
}

__global__ void scan_addback(const int* __restrict__ bsumx, int* __restrict__ rowptr)
{
    const int op = blockIdx.y;
    int i = blockIdx.x * blockDim.x + threadIdx.x;
    int* rp = rowptr + op * (N_NODES + 1);
    if (i < N_NODES)
        rp[i] += bsumx[op * (NB_SCAN + 1) + (i >> 10)];
    if (i == N_NODES) rp[N_NODES] = N_EDGES;
}

__global__ void scatter_edges(const int* __restrict__ i0, const int* __restrict__ i1,
                              const int* __restrict__ i2, const int* __restrict__ i3,
                              const float* __restrict__ v0, const float* __restrict__ v1,
                              const float* __restrict__ v2, const float* __restrict__ v3,
                              const int* __restrict__ rowptr,
                              const unsigned* __restrict__ rank,
                              int2* __restrict__ out)
{
    const int op = blockIdx.y;
    const int*   idx = (op == 0) ? i0 : (op == 1) ? i1 : (op == 2) ? i2 : i3;
    const float* val = (op == 0) ? v0 : (op == 1) ? v1 : (op == 2) ? v2 : v3;
    int e = (blockIdx.x * blockDim.x + threadIdx.x) * 2;
    if (e + 1 < N_EDGES) {
        int2   cc = *(const int2*)(idx + N_EDGES + e);     // source cols
        float2 vv = *(const float2*)(val + e);
        uint2  pk = *(const uint2*)(rank + (size_t)op * N_EDGES + e);
        const int* rp = rowptr + op * (N_NODES + 1);
        int pos0 = rp[pk.x >> 15] + (int)(pk.x & 0x7fffu);
        int pos1 = rp[pk.y >> 15] + (int)(pk.y & 0x7fffu);
        int2* ob = out + (size_t)op * N_EDGES;
        ob[pos0] = make_int2(cc.x, __float_as_int(vv.x));
        ob[pos1] = make_int2(cc.y, __float_as_int(vv.y));
    }
}

// ---------------------------------------------------------------------------
// CSR SPMM core: shfl-staged edges (1 coalesced LDG per 32 edges/lane),
// fp16 gather via __ldcg (L2-only, no L1 allocate: zero-reuse working set),
// fp32 accumulate, fp16 output.
// ---------------------------------------------------------------------------
__device__ __forceinline__ float2 gather_h2(const __half* in, int c, int lane)
{
    __half2 h = __ldcg((const __half2*)(in + (size_t)c * F_OUT) + lane);
    return __half22float2(h);
}

__device__ __forceinline__ void spmm_row_h(const int* __restrict__ rowptr,
                                           const int2* __restrict__ eg,
                                           const __half* __restrict__ in,
                                           __half* __restrict__ out,
                                           int warp, int lane)
{
    const int s = rowptr[warp];
    const int e = rowptr[warp + 1];
    float ax = 0.f, ay = 0.f;

    for (int b = s; b < e; b += 32) {
        const int m = min(32, e - b);
        int2 ed = make_int2(0, 0);
        if (lane < m) ed = eg[b + lane];

        int j = 0;
        for (; j + 4 <= m; j += 4) {
            int   c0 = __shfl_sync(0xffffffffu, ed.x, j);
            int   c1 = __shfl_sync(0xffffffffu, ed.x, j + 1);
            int   c2 = __shfl_sync(0xffffffffu, ed.x, j + 2);
            int   c3 = __shfl_sync(0xffffffffu, ed.x, j + 3);
            float v0 = __int_as_float(__shfl_sync(0xffffffffu, ed.y, j));
            float v1 = __int_as_float(__shfl_sync(0xffffffffu, ed.y, j + 1));
            float v2 = __int_as_float(__shfl_sync(0xffffffffu, ed.y, j + 2));
            float v3 = __int_as_float(__shfl_sync(0xffffffffu, ed.y, j + 3));
            float2 x0 = gather_h2(in, c0, lane);
            float2 x1 = gather_h2(in, c1, lane);
            float2 x2 = gather_h2(in, c2, lane);
            float2 x3 = gather_h2(in, c3, lane);
            ax = fmaf(v0, x0.x, ax); ay = fmaf(v0, x0.y, ay);
            ax = fmaf(v1, x1.x, ax); ay = fmaf(v1, x1.y, ay);
            ax = fmaf(v2, x2.x, ax); ay = fmaf(v2, x2.y, ay);
            ax = fmaf(v3, x3.x, ax); ay = fmaf(v3, x3.y, ay);
        }
        for (; j < m; j++) {
            int   c = __shfl_sync(0xffffffffu, ed.x, j);
            float v = __int_as_float(__shfl_sync(0xffffffffu, ed.y, j));
            float2 xv = gather_h2(in, c, lane);
            ax = fmaf(v, xv.x, ax); ay = fmaf(v, xv.y, ay);
        }
    }

    *((__half2*)(out + (size_t)warp * F_OUT) + lane) = __floats2half2_rn(ax, ay);
}

// Fused launch: y=0 -> A·s0 (channel 0), y=1..3 -> P1..P3 (channels 3..5).
__global__ void spmm_fused4(const int* __restrict__ rowptr_all,
                            const int2* __restrict__ eg_all,
                            const __half* __restrict__ s0h,
                            __half* __restrict__ acch)
{
    const int op = blockIdx.y;                       // 0..3
    const int warp = (blockIdx.x * blockDim.x + threadIdx.x) >> 5;
    const int lane = threadIdx.x & 31;
    if (warp >= N_NODES) return;

    const int*  rowptr = rowptr_all + op * (N_NODES + 1);
    const int2* eg     = eg_all + (size_t)op * N_EDGES;
    __half* out = acch + (size_t)((op == 0) ? 0 : op + 2) * NF;
    spmm_row_h(rowptr, eg, s0h, out, warp, lane);
}

// Single chain hop: gather fp16 'in', write fp16 'out'.
__global__ void spmm_hop(const int* __restrict__ rowptr, const int2* __restrict__ eg,
                         const __half* __restrict__ in, __half* __restrict__ out)
{
    const int warp = (blockIdx.x * blockDim.x + threadIdx.x) >> 5;
    const int lane = threadIdx.x & 31;
    if (warp >= N_NODES) return;
    spmm_row_h(rowptr, eg, in, out, warp, lane);
}

// ---------------------------------------------------------------------------
// Finalize (channels read fp16)
// ---------------------------------------------------------------------------
__global__ void finalize(const float* __restrict__ s0, const float* __restrict__ a,
                         float* __restrict__ out_hp, float* __restrict__ out_att)
{
    __shared__ float ch[8][6][64];
    __shared__ float as[768];

    const int tid = threadIdx.x;
    for (int i = tid; i < 768; i += 256) as[i] = a[i];

    const int w    = tid >> 5;
    const int lane = tid & 31;
    const int r    = blockIdx.x * 8 + w;
    __syncthreads();

    #pragma unroll
    for (int c = 0; c < 6; c++) {
        float2 v = __half22float2(*((const __half2*)(g_acch[c]) + (size_t)r * 32 + lane));
        if (c >= 3) { v.x = fabsf(v.x); v.y = fabsf(v.y); }
        ch[w][c][2 * lane]     = v.x;
        ch[w][c][2 * lane + 1] = v.y;
    }
    __syncwarp();

    float p[6];
    if (r < N_NODES / 2) {
        size_t b0 = (size_t)(2 * r) * F_OUT;
        size_t b1 = (size_t)(2 * r + 1) * F_OUT;
        float2 u = *(const float2*)(s0 + b0 + 2 * lane);
        float2 t = *(const float2*)(s0 + b1 + 2 * lane);
        #pragma unroll
        for (int i = 0; i < 6; i++) {
            const float* ai = as + i * 128;
            p[i] = ai[2 * lane] * u.x + ai[2 * lane + 1] * u.y
                 + ai[64 + 2 * lane] * t.x + ai[64 + 2 * lane + 1] * t.y;
        }
    } else {
        int q = 2 * r - N_NODES;
        #pragma unroll
        for (int i = 0; i < 6; i++) {
            float2 u = __half22float2(*((const __half2*)(g_acch[i]) + (size_t)q * 32 + lane));
            float2 t = __half22float2(*((const __half2*)(g_acch[i]) + (size_t)(q + 1) * 32 + lane));
            if (i >= 3) { u.x = fabsf(u.x); u.y = fabsf(u.y); t.x = fabsf(t.x); t.y = fabsf(t.y); }
            const float* ai = as + i * 128;
            p[i] = ai[2 * lane] * u.x + ai[2 * lane + 1] * u.y
                 + ai[64 + 2 * lane] * t.x + ai[64 + 2 * lane + 1] * t.y;
        }
    }

    #pragma unroll
    for (int i = 0; i < 6; i++) {
        #pragma unroll
        for (int off = 16; off; off >>= 1)
            p[i] += __shfl_down_sync(0xffffffffu, p[i], off);
        p[i] = __shfl_sync(0xffffffffu, p[i], 0);
    }

    float m = p[0];
    #pragma unroll
    for (int i = 1; i < 6; i++) m = fmaxf(m, p[i]);
    float att[6], s = 0.f;
    #pragma unroll
    for (int i = 0; i < 6; i++) { att[i] = expf(p[i] - m); s += att[i]; }
    float inv = 1.f / s;
    #pragma unroll
    for (int i = 0; i < 6; i++) att[i] *= inv;

    if (out_att && lane == 0) {
        #pragma unroll
        for (int i = 0; i < 6; i++) out_att[(size_t)r * 6 + i] = att[i];
    }

    #pragma unroll
    for (int kk = 0; kk < 2; kk++) {
        int k = lane + kk * 32;
        float hp = 0.f;
        #pragma unroll
        for (int j = 0; j < 6; j++) {
            int idx = j * 64 + k;
            hp = fmaf(att[j], ch[w][idx % 6][idx / 6], hp);
        }
        out_hp[(size_t)r * F_OUT + k] = hp * (1.0f / 6.0f);
    }
}

// ---------------------------------------------------------------------------
extern "C" void kernel_launch(void* const* d_in, const int* in_sizes, int n_in,
                              void* d_out, int out_size)
{
    const float* x  = (const float*)d_in[0];
    const float* W  = (const float*)d_in[1];
    const float* a  = (const float*)d_in[2];
    const int*   iA  = (const int*)d_in[3];   const float* vA  = (const float*)d_in[4];
    const int*   iP1 = (const int*)d_in[5];   const float* vP1 = (const float*)d_in[6];
    const int*   iP2 = (const int*)d_in[7];   const float* vP2 = (const float*)d_in[8];
    const int*   iP3 = (const int*)d_in[9];   const float* vP3 = (const float*)d_in[10];

    float*    s0;   cudaGetSymbolAddress((void**)&s0,   g_s0);
    __half*   s0h;  cudaGetSymbolAddress((void**)&s0h,  g_s0h);
    __half*   acch; cudaGetSymbolAddress((void**)&acch, g_acch);
    int*      cnt;  cudaGetSymbolAddress((void**)&cnt,  g_cnt);
    int*      rp;   cudaGetSymbolAddress((void**)&rp,   g_rowptr);
    unsigned* rk;   cudaGetSymbolAddress((void**)&rk,   g_rank);
    int2*     eg;   cudaGetSymbolAddress((void**)&eg,   g_edges);
    int*      bs;   cudaGetSymbolAddress((void**)&bs,   g_bsum);
    int*      bsx;  cudaGetSymbolAddress((void**)&bsx,  g_bsumx);

    // One-time host-side resources (no device memory).
    static cudaStream_t s_side = nullptr;
    static cudaEvent_t  ev_fork = nullptr, ev_join = nullptr;
    if (!s_side) {
        cudaStreamCreateWithFlags(&s_side, cudaStreamNonBlocking);
        cudaEventCreateWithFlags(&ev_fork, cudaEventDisableTiming);
        cudaEventCreateWithFlags(&ev_join, cudaEventDisableTiming);
    }

    // Fork: CSR build on side stream, GEMM on main stream (independent).
    cudaEventRecord(ev_fork, 0);
    cudaStreamWaitEvent(s_side, ev_fork, 0);

    gemm64<<<(N_NODES + 63) / 64, 128>>>(x, W, s0, s0h);

    cudaMemsetAsync(cnt, 0, sizeof(int) * 4 * N_NODES, s_side);
    const dim3 EG2((N_EDGES / 2 + 255) / 256, 4);
    hist_rank<<<EG2, 256, 0, s_side>>>(iA, iP1, iP2, iP3, cnt, rk);
    scan_blocks<<<dim3(NB_SCAN, 4), 256, 0, s_side>>>(cnt, rp, bs);
    scan_bsums<<<1, 128, 0, s_side>>>(bs, bsx);
    scan_addback<<<dim3((N_NODES + 256) / 256, 4), 256, 0, s_side>>>(bsx, rp);
    scatter_edges<<<EG2, 256, 0, s_side>>>(iA, iP1, iP2, iP3, vA, vP1, vP2, vP3,
                                           rp, rk, eg);

    cudaEventRecord(ev_join, s_side);
    cudaStreamWaitEvent(0, ev_join, 0);

    const int SG = (N_NODES * 32 + 255) / 256;
    // Fused: A·s0 -> ch0, P1..P3 -> ch3..5 (fp16 gather from s0h)
    spmm_fused4<<<dim3(SG, 4), 256>>>(rp, eg, s0h, acch);
    // Chain hops 2,3 (fp16 in/out)
    spmm_hop<<<SG, 256>>>(rp, eg, acch + 0 * (size_t)NF, acch + 1 * (size_t)NF);
    spmm_hop<<<SG, 256>>>(rp, eg, acch + 1 * (size_t)NF, acch + 2 * (size_t)NF);

    float* out = (float*)d_out;
    float* att = (out_size >= N_NODES * F_OUT + N_NODES * 6)
                     ? out + (size_t)N_NODES * F_OUT : nullptr;
    finalize<<<N_NODES / 8, 256>>>(s0, a, out, att);
}

// round 15
// speedup vs baseline: 1.1208x; 1.1208x over previous
#include <cuda_runtime.h>
#include <cuda_fp16.h>
#include <cstddef>

#define N_NODES 100000
#define N_EDGES 3200000
#define F_IN    256
#define F_OUT   64
#define NF      (N_NODES * F_OUT)
#define SCAN_BLK 1024
#define NB_SCAN  ((N_NODES + SCAN_BLK - 1) / SCAN_BLK)   // 98

// Scratch (device globals; allocation-free).
__device__ float    g_s0[NF];
__device__ __half   g_s0h[NF];            // fp16 s0 (gather source)
__device__ __half   g_acch[6][NF];        // fp16 channels: hA,hA2,hA3,hs1,hs2,hs3
__device__ int      g_cnt[4][N_NODES];
__device__ int      g_rowptr[4][N_NODES + 1];
__device__ unsigned g_rank[4][N_EDGES];   // packed (row<<15)|rank
__device__ int2     g_edges[4][N_EDGES];  // (col, val-as-int), dest-sorted
__device__ int      g_bsum[4][NB_SCAN + 1];
__device__ int      g_bsumx[4][NB_SCAN + 1];

// ---------------------------------------------------------------------------
// GEMM: s0[N,64] = x[N,256] @ W[256,64], fp32; also emits fp16 copy.
// ---------------------------------------------------------------------------
__global__ void gemm64(const float* __restrict__ x, const float* __restrict__ W,
                       float* __restrict__ out, __half* __restrict__ outh)
{
    __shared__ float xs[32][64];
    __shared__ float ws[32][64];

    const int tid = threadIdx.x;       // 0..127
    const int tx  = tid & 7;
    const int ty  = tid >> 3;
    const int r0  = blockIdx.x * 64;

    float4 acc0[4] = {};
    float4 acc1[4] = {};

    for (int k0 = 0; k0 < F_IN; k0 += 32) {
        #pragma unroll
        for (int it = 0; it < 4; it++) {
            int li  = it * 128 + tid;
            int row = li >> 3;
            int kq  = li & 7;
            float4 v = make_float4(0.f, 0.f, 0.f, 0.f);
            int gr = r0 + row;
            if (gr < N_NODES)
                v = *(const float4*)(x + (size_t)gr * F_IN + k0 + kq * 4);
            xs[kq * 4 + 0][row] = v.x;
            xs[kq * 4 + 1][row] = v.y;
            xs[kq * 4 + 2][row] = v.z;
            xs[kq * 4 + 3][row] = v.w;
        }
        #pragma unroll
        for (int it = 0; it < 4; it++) {
            int li = it * 128 + tid;
            int kk = li >> 4;
            int cq = li & 15;
            *(float4*)&ws[kk][cq * 4] =
                *(const float4*)(W + (size_t)(k0 + kk) * F_OUT + cq * 4);
        }
        __syncthreads();

        #pragma unroll
        for (int kk = 0; kk < 32; kk++) {
            float4 av = *(const float4*)&xs[kk][ty * 4];
            float4 b0 = *(const float4*)&ws[kk][tx * 4];
            float4 b1 = *(const float4*)&ws[kk][tx * 4 + 32];
            float a4[4] = {av.x, av.y, av.z, av.w};
            #pragma unroll
            for (int j = 0; j < 4; j++) {
                acc0[j].x = fmaf(a4[j], b0.x, acc0[j].x);
                acc0[j].y = fmaf(a4[j], b0.y, acc0[j].y);
                acc0[j].z = fmaf(a4[j], b0.z, acc0[j].z);
                acc0[j].w = fmaf(a4[j], b0.w, acc0[j].w);
                acc1[j].x = fmaf(a4[j], b1.x, acc1[j].x);
                acc1[j].y = fmaf(a4[j], b1.y, acc1[j].y);
                acc1[j].z = fmaf(a4[j], b1.z, acc1[j].z);
                acc1[j].w = fmaf(a4[j], b1.w, acc1[j].w);
            }
        }
        __syncthreads();
    }

    #pragma unroll
    for (int j = 0; j < 4; j++) {
        int gr = r0 + ty * 4 + j;
        if (gr < N_NODES) {
            *(float4*)(out + (size_t)gr * F_OUT + tx * 4)      = acc0[j];
            *(float4*)(out + (size_t)gr * F_OUT + tx * 4 + 32) = acc1[j];
            __half2* hp = (__half2*)(outh + (size_t)gr * F_OUT);
            hp[tx * 2]      = __floats2half2_rn(acc0[j].x, acc0[j].y);
            hp[tx * 2 + 1]  = __floats2half2_rn(acc0[j].z, acc0[j].w);
            hp[tx * 2 + 16] = __floats2half2_rn(acc1[j].x, acc1[j].y);
            hp[tx * 2 + 17] = __floats2half2_rn(acc1[j].z, acc1[j].w);
        }
    }
}

// ---------------------------------------------------------------------------
// CSR build (fused across 4 operators via blockIdx.y); 4 edges per thread
// for MLP (latency-bound kernels per ncu: issue ~7%, L2 ~67%).
// ---------------------------------------------------------------------------
__global__ void hist_rank(const int* __restrict__ i0, const int* __restrict__ i1,
                          const int* __restrict__ i2, const int* __restrict__ i3,
                          int* __restrict__ cnt, unsigned* __restrict__ rank)
{
    const int op = blockIdx.y;
    const int* idx = (op == 0) ? i0 : (op == 1) ? i1 : (op == 2) ? i2 : i3;
    int e = (blockIdx.x * blockDim.x + threadIdx.x) * 4;
    if (e + 3 < N_EDGES) {
        int4 rr = *(const int4*)(idx + e);
        unsigned k0 = atomicAdd(&cnt[op * N_NODES + rr.x], 1);
        unsigned k1 = atomicAdd(&cnt[op * N_NODES + rr.y], 1);
        unsigned k2 = atomicAdd(&cnt[op * N_NODES + rr.z], 1);
        unsigned k3 = atomicAdd(&cnt[op * N_NODES + rr.w], 1);
        uint4 pk = make_uint4(((unsigned)rr.x << 15) | k0,
                              ((unsigned)rr.y << 15) | k1,
                              ((unsigned)rr.z << 15) | k2,
                              ((unsigned)rr.w << 15) | k3);
        *(uint4*)(rank + (size_t)op * N_EDGES + e) = pk;
    }
}

__global__ void scan_blocks(const int* __restrict__ cnt, int* __restrict__ excl,
                            int* __restrict__ bsum)
{
    __shared__ int sh[256];
    const int op = blockIdx.y;
    const int t = threadIdx.x;
    const int base = blockIdx.x * SCAN_BLK + t * 4;
    const int* c = cnt + op * N_NODES;
    int* ex = excl + op * (N_NODES + 1);

    int v[4];
    #pragma unroll
    for (int i = 0; i < 4; i++)
        v[i] = (base + i < N_NODES) ? c[base + i] : 0;
    int s = v[0] + v[1] + v[2] + v[3];
    sh[t] = s;
    __syncthreads();
    #pragma unroll
    for (int off = 1; off < 256; off <<= 1) {
        int x = (t >= off) ? sh[t - off] : 0;
        __syncthreads();
        sh[t] += x;
        __syncthreads();
    }
    int run = sh[t] - s;
    #pragma unroll
    for (int i = 0; i < 4; i++) {
        if (base + i < N_NODES) ex[base + i] = run;
        run += v[i];
    }
    if (t == 255) bsum[op * (NB_SCAN + 1) + blockIdx.x] = sh[255];
}

__global__ void scan_bsums(const int* __restrict__ bsum, int* __restrict__ bsumx)
{
    const int op   = threadIdx.x >> 5;
    const int lane = threadIdx.x & 31;
    const int* b = bsum  + op * (NB_SCAN + 1);
    int*      bx = bsumx + op * (NB_SCAN + 1);
    int carry = 0;
    #pragma unroll
    for (int c = 0; c < (NB_SCAN + 31) / 32; c++) {
        int i = c * 32 + lane;
        int v = (i < NB_SCAN) ? b[i] : 0;
        int s = v;
        #pragma unroll
        for (int off = 1; off < 32; off <<= 1) {
            int t = __shfl_up_sync(0xffffffffu, s, off);
            if (lane >= off) s += t;
        }
        if (i < NB_SCAN) bx[i] = carry + s - v;
        carry += __shfl_sync(0xffffffffu, s, 31);
    }
}

__global__ void scan_addback(const int* __restrict__ bsumx, int* __restrict__ rowptr)
{
    const int op = blockIdx.y;
    int i = blockIdx.x * blockDim.x + threadIdx.x;
    int* rp = rowptr + op * (N_NODES + 1);
    if (i < N_NODES)
        rp[i] += bsumx[op * (NB_SCAN + 1) + (i >> 10)];
    if (i == N_NODES) rp[N_NODES] = N_EDGES;
}

__global__ void scatter_edges(const int* __restrict__ i0, const int* __restrict__ i1,
                              const int* __restrict__ i2, const int* __restrict__ i3,
                              const float* __restrict__ v0, const float* __restrict__ v1,
                              const float* __restrict__ v2, const float* __restrict__ v3,
                              const int* __restrict__ rowptr,
                              const unsigned* __restrict__ rank,
                              int2* __restrict__ out)
{
    const int op = blockIdx.y;
    const int*   idx = (op == 0) ? i0 : (op == 1) ? i1 : (op == 2) ? i2 : i3;
    const float* val = (op == 0) ? v0 : (op == 1) ? v1 : (op == 2) ? v2 : v3;
    int e = (blockIdx.x * blockDim.x + threadIdx.x) * 4;
    if (e + 3 < N_EDGES) {
        int4   cc = *(const int4*)(idx + N_EDGES + e);     // source cols
        float4 vv = *(const float4*)(val + e);
        uint4  pk = *(const uint4*)(rank + (size_t)op * N_EDGES + e);
        const int* rp = rowptr + op * (N_NODES + 1);
        int pos0 = rp[pk.x >> 15] + (int)(pk.x & 0x7fffu);
        int pos1 = rp[pk.y >> 15] + (int)(pk.y & 0x7fffu);
        int pos2 = rp[pk.z >> 15] + (int)(pk.z & 0x7fffu);
        int pos3 = rp[pk.w >> 15] + (int)(pk.w & 0x7fffu);
        int2* ob = out + (size_t)op * N_EDGES;
        ob[pos0] = make_int2(cc.x, __float_as_int(vv.x));
        ob[pos1] = make_int2(cc.y, __float_as_int(vv.y));
        ob[pos2] = make_int2(cc.z, __float_as_int(vv.z));
        ob[pos3] = make_int2(cc.w, __float_as_int(vv.w));
    }
}

// ---------------------------------------------------------------------------
// CSR SPMM core (round-8/13 champion): shfl-staged edges, default-cached
// half2 gathers (L1 reuse is real: aggregate L1 > working set), fp32
// accumulate, fp16 output.
// ---------------------------------------------------------------------------
__device__ __forceinline__ void spmm_row_h(const int* __restrict__ rowptr,
                                           const int2* __restrict__ eg,
                                           const __half* __restrict__ in,
                                           __half* __restrict__ out,
                                           int warp, int lane)
{
    const int s = rowptr[warp];
    const int e = rowptr[warp + 1];
    float ax = 0.f, ay = 0.f;

    for (int b = s; b < e; b += 32) {
        const int m = min(32, e - b);
        int2 ed = make_int2(0, 0);
        if (lane < m) ed = eg[b + lane];

        int j = 0;
        for (; j + 4 <= m; j += 4) {
            int   c0 = __shfl_sync(0xffffffffu, ed.x, j);
            int   c1 = __shfl_sync(0xffffffffu, ed.x, j + 1);
            int   c2 = __shfl_sync(0xffffffffu, ed.x, j + 2);
            int   c3 = __shfl_sync(0xffffffffu, ed.x, j + 3);
            float v0 = __int_as_float(__shfl_sync(0xffffffffu, ed.y, j));
            float v1 = __int_as_float(__shfl_sync(0xffffffffu, ed.y, j + 1));
            float v2 = __int_as_float(__shfl_sync(0xffffffffu, ed.y, j + 2));
            float v3 = __int_as_float(__shfl_sync(0xffffffffu, ed.y, j + 3));
            float2 x0 = __half22float2(*((const __half2*)(in + (size_t)c0 * F_OUT) + lane));
            float2 x1 = __half22float2(*((const __half2*)(in + (size_t)c1 * F_OUT) + lane));
            float2 x2 = __half22float2(*((const __half2*)(in + (size_t)c2 * F_OUT) + lane));
            float2 x3 = __half22float2(*((const __half2*)(in + (size_t)c3 * F_OUT) + lane));
            ax = fmaf(v0, x0.x, ax); ay = fmaf(v0, x0.y, ay);
            ax = fmaf(v1, x1.x, ax); ay = fmaf(v1, x1.y, ay);
            ax = fmaf(v2, x2.x, ax); ay = fmaf(v2, x2.y, ay);
            ax = fmaf(v3, x3.x, ax); ay = fmaf(v3, x3.y, ay);
        }
        for (; j < m; j++) {
            int   c = __shfl_sync(0xffffffffu, ed.x, j);
            float v = __int_as_float(__shfl_sync(0xffffffffu, ed.y, j));
            float2 xv = __half22float2(*((const __half2*)(in + (size_t)c * F_OUT) + lane));
            ax = fmaf(v, xv.x, ax); ay = fmaf(v, xv.y, ay);
        }
    }

    *((__half2*)(out + (size_t)warp * F_OUT) + lane) = __floats2half2_rn(ax, ay);
}

// Fused launch: y=0 -> A·s0 (channel 0), y=1..3 -> P1..P3 (channels 3..5).
__global__ void spmm_fused4(const int* __restrict__ rowptr_all,
                            const int2* __restrict__ eg_all,
                            const __half* __restrict__ s0h,
                            __half* __restrict__ acch)
{
    const int op = blockIdx.y;                       // 0..3
    const int warp = (blockIdx.x * blockDim.x + threadIdx.x) >> 5;
    const int lane = threadIdx.x & 31;
    if (warp >= N_NODES) return;

    const int*  rowptr = rowptr_all + op * (N_NODES + 1);
    const int2* eg     = eg_all + (size_t)op * N_EDGES;
    __half* out = acch + (size_t)((op == 0) ? 0 : op + 2) * NF;
    spmm_row_h(rowptr, eg, s0h, out, warp, lane);
}

// Single chain hop: gather fp16 'in', write fp16 'out'.
__global__ void spmm_hop(const int* __restrict__ rowptr, const int2* __restrict__ eg,
                         const __half* __restrict__ in, __half* __restrict__ out)
{
    const int warp = (blockIdx.x * blockDim.x + threadIdx.x) >> 5;
    const int lane = threadIdx.x & 31;
    if (warp >= N_NODES) return;
    spmm_row_h(rowptr, eg, in, out, warp, lane);
}

// ---------------------------------------------------------------------------
// Finalize (channels read fp16)
// ---------------------------------------------------------------------------
__global__ void finalize(const float* __restrict__ s0, const float* __restrict__ a,
                         float* __restrict__ out_hp, float* __restrict__ out_att)
{
    __shared__ float ch[8][6][64];
    __shared__ float as[768];

    const int tid = threadIdx.x;
    for (int i = tid; i < 768; i += 256) as[i] = a[i];

    const int w    = tid >> 5;
    const int lane = tid & 31;
    const int r    = blockIdx.x * 8 + w;
    __syncthreads();

    #pragma unroll
    for (int c = 0; c < 6; c++) {
        float2 v = __half22float2(*((const __half2*)(g_acch[c]) + (size_t)r * 32 + lane));
        if (c >= 3) { v.x = fabsf(v.x); v.y = fabsf(v.y); }
        ch[w][c][2 * lane]     = v.x;
        ch[w][c][2 * lane + 1] = v.y;
    }
    __syncwarp();

    float p[6];
    if (r < N_NODES / 2) {
        size_t b0 = (size_t)(2 * r) * F_OUT;
        size_t b1 = (size_t)(2 * r + 1) * F_OUT;
        float2 u = *(const float2*)(s0 + b0 + 2 * lane);
        float2 t = *(const float2*)(s0 + b1 + 2 * lane);
        #pragma unroll
        for (int i = 0; i < 6; i++) {
            const float* ai = as + i * 128;
            p[i] = ai[2 * lane] * u.x + ai[2 * lane + 1] * u.y
                 + ai[64 + 2 * lane] * t.x + ai[64 + 2 * lane + 1] * t.y;
        }
    } else {
        int q = 2 * r - N_NODES;
        #pragma unroll
        for (int i = 0; i < 6; i++) {
            float2 u = __half22float2(*((const __half2*)(g_acch[i]) + (size_t)q * 32 + lane));
            float2 t = __half22float2(*((const __half2*)(g_acch[i]) + (size_t)(q + 1) * 32 + lane));
            if (i >= 3) { u.x = fabsf(u.x); u.y = fabsf(u.y); t.x = fabsf(t.x); t.y = fabsf(t.y); }
            const float* ai = as + i * 128;
            p[i] = ai[2 * lane] * u.x + ai[2 * lane + 1] * u.y
                 + ai[64 + 2 * lane] * t.x + ai[64 + 2 * lane + 1] * t.y;
        }
    }

    #pragma unroll
    for (int i = 0; i < 6; i++) {
        #pragma unroll
        for (int off = 16; off; off >>= 1)
            p[i] += __shfl_down_sync(0xffffffffu, p[i], off);
        p[i] = __shfl_sync(0xffffffffu, p[i], 0);
    }

    float m = p[0];
    #pragma unroll
    for (int i = 1; i < 6; i++) m = fmaxf(m, p[i]);
    float att[6], s = 0.f;
    #pragma unroll
    for (int i = 0; i < 6; i++) { att[i] = expf(p[i] - m); s += att[i]; }
    float inv = 1.f / s;
    #pragma unroll
    for (int i = 0; i < 6; i++) att[i] *= inv;

    if (out_att && lane == 0) {
        #pragma unroll
        for (int i = 0; i < 6; i++) out_att[(size_t)r * 6 + i] = att[i];
    }

    #pragma unroll
    for (int kk = 0; kk < 2; kk++) {
        int k = lane + kk * 32;
        float hp = 0.f;
        #pragma unroll
        for (int j = 0; j < 6; j++) {
            int idx = j * 64 + k;
            hp = fmaf(att[j], ch[w][idx % 6][idx / 6], hp);
        }
        out_hp[(size_t)r * F_OUT + k] = hp * (1.0f / 6.0f);
    }
}

// ---------------------------------------------------------------------------
extern "C" void kernel_launch(void* const* d_in, const int* in_sizes, int n_in,
                              void* d_out, int out_size)
{
    const float* x  = (const float*)d_in[0];
    const float* W  = (const float*)d_in[1];
    const float* a  = (const float*)d_in[2];
    const int*   iA  = (const int*)d_in[3];   const float* vA  = (const float*)d_in[4];
    const int*   iP1 = (const int*)d_in[5];   const float* vP1 = (const float*)d_in[6];
    const int*   iP2 = (const int*)d_in[7];   const float* vP2 = (const float*)d_in[8];
    const int*   iP3 = (const int*)d_in[9];   const float* vP3 = (const float*)d_in[10];

    float*    s0;   cudaGetSymbolAddress((void**)&s0,   g_s0);
    __half*   s0h;  cudaGetSymbolAddress((void**)&s0h,  g_s0h);
    __half*   acch; cudaGetSymbolAddress((void**)&acch, g_acch);
    int*      cnt;  cudaGetSymbolAddress((void**)&cnt,  g_cnt);
    int*      rp;   cudaGetSymbolAddress((void**)&rp,   g_rowptr);
    unsigned* rk;   cudaGetSymbolAddress((void**)&rk,   g_rank);
    int2*     eg;   cudaGetSymbolAddress((void**)&eg,   g_edges);
    int*      bs;   cudaGetSymbolAddress((void**)&bs,   g_bsum);
    int*      bsx;  cudaGetSymbolAddress((void**)&bsx,  g_bsumx);

    // One-time host-side resources (no device memory).
    static cudaStream_t s_side = nullptr;
    static cudaEvent_t  ev_fork = nullptr, ev_join = nullptr;
    if (!s_side) {
        cudaStreamCreateWithFlags(&s_side, cudaStreamNonBlocking);
        cudaEventCreateWithFlags(&ev_fork, cudaEventDisableTiming);
        cudaEventCreateWithFlags(&ev_join, cudaEventDisableTiming);
    }

    // Fork: CSR build on side stream, GEMM on main stream (independent).
    cudaEventRecord(ev_fork, 0);
    cudaStreamWaitEvent(s_side, ev_fork, 0);

    gemm64<<<(N_NODES + 63) / 64, 128>>>(x, W, s0, s0h);

    cudaMemsetAsync(cnt, 0, sizeof(int) * 4 * N_NODES, s_side);
    const dim3 EG4((N_EDGES / 4 + 255) / 256, 4);      // 4 edges per thread
    hist_rank<<<EG4, 256, 0, s_side>>>(iA, iP1, iP2, iP3, cnt, rk);
    scan_blocks<<<dim3(NB_SCAN, 4), 256, 0, s_side>>>(cnt, rp, bs);
    scan_bsums<<<1, 128, 0, s_side>>>(bs, bsx);
    scan_addback<<<dim3((N_NODES + 256) / 256, 4), 256, 0, s_side>>>(bsx, rp);
    scatter_edges<<<EG4, 256, 0, s_side>>>(iA, iP1, iP2, iP3, vA, vP1, vP2, vP3,
                                           rp, rk, eg);

    cudaEventRecord(ev_join, s_side);
    cudaStreamWaitEvent(0, ev_join, 0);

    const int SG = (N_NODES * 32 + 255) / 256;
    // Fused: A·s0 -> ch0, P1..P3 -> ch3..5 (fp16 gather from s0h)
    spmm_fused4<<<dim3(SG, 4), 256>>>(rp, eg, s0h, acch);
    // Chain hops 2,3 (fp16 in/out)
    spmm_hop<<<SG, 256>>>(rp, eg, acch + 0 * (size_t)NF, acch + 1 * (size_t)NF);
    spmm_hop<<<SG, 256>>>(rp, eg, acch + 1 * (size_t)NF, acch + 2 * (size_t)NF);

    float* out = (float*)d_out;
    float* att = (out_size >= N_NODES * F_OUT + N_NODES * 6)
                     ? out + (size_t)N_NODES * F_OUT : nullptr;
    finalize<<<N_NODES / 8, 256>>>(s0, a, out, att);
}

// round 16
// speedup vs baseline: 1.1609x; 1.0358x over previous
#include <cuda_runtime.h>
#include <cuda_fp16.h>
#include <cstddef>

#define N_NODES 100000
#define N_EDGES 3200000
#define F_IN    256
#define F_OUT   64
#define NF      (N_NODES * F_OUT)
#define SCAN_BLK 1024
#define NB_SCAN  ((N_NODES + SCAN_BLK - 1) / SCAN_BLK)   // 98

// Scratch (device globals; allocation-free).
__device__ float    g_s0[NF];
__device__ __half   g_s0h[NF];            // fp16 s0 (gather source)
__device__ __half   g_acch[6][NF];        // fp16 channels: hA,hA2,hA3,hs1,hs2,hs3
__device__ int      g_cnt[4][N_NODES];
__device__ int      g_rowptr[4][N_NODES + 1];
__device__ unsigned g_rank[4][N_EDGES];   // packed (row<<15)|rank
__device__ int2     g_edges[4][N_EDGES];  // (col, val-as-int), dest-sorted
__device__ int      g_bsum[4][NB_SCAN + 1];
__device__ int      g_bsumx[4][NB_SCAN + 1];

// ---------------------------------------------------------------------------
// GEMM: s0[N,64] = x[N,256] @ W[256,64], fp32; also emits fp16 copy.
// ---------------------------------------------------------------------------
__global__ void gemm64(const float* __restrict__ x, const float* __restrict__ W,
                       float* __restrict__ out, __half* __restrict__ outh)
{
    __shared__ float xs[32][64];
    __shared__ float ws[32][64];

    const int tid = threadIdx.x;       // 0..127
    const int tx  = tid & 7;
    const int ty  = tid >> 3;
    const int r0  = blockIdx.x * 64;

    float4 acc0[4] = {};
    float4 acc1[4] = {};

    for (int k0 = 0; k0 < F_IN; k0 += 32) {
        #pragma unroll
        for (int it = 0; it < 4; it++) {
            int li  = it * 128 + tid;
            int row = li >> 3;
            int kq  = li & 7;
            float4 v = make_float4(0.f, 0.f, 0.f, 0.f);
            int gr = r0 + row;
            if (gr < N_NODES)
                v = *(const float4*)(x + (size_t)gr * F_IN + k0 + kq * 4);
            xs[kq * 4 + 0][row] = v.x;
            xs[kq * 4 + 1][row] = v.y;
            xs[kq * 4 + 2][row] = v.z;
            xs[kq * 4 + 3][row] = v.w;
        }
        #pragma unroll
        for (int it = 0; it < 4; it++) {
            int li = it * 128 + tid;
            int kk = li >> 4;
            int cq = li & 15;
            *(float4*)&ws[kk][cq * 4] =
                *(const float4*)(W + (size_t)(k0 + kk) * F_OUT + cq * 4);
        }
        __syncthreads();

        #pragma unroll
        for (int kk = 0; kk < 32; kk++) {
            float4 av = *(const float4*)&xs[kk][ty * 4];
            float4 b0 = *(const float4*)&ws[kk][tx * 4];
            float4 b1 = *(const float4*)&ws[kk][tx * 4 + 32];
            float a4[4] = {av.x, av.y, av.z, av.w};
            #pragma unroll
            for (int j = 0; j < 4; j++) {
                acc0[j].x = fmaf(a4[j], b0.x, acc0[j].x);
                acc0[j].y = fmaf(a4[j], b0.y, acc0[j].y);
                acc0[j].z = fmaf(a4[j], b0.z, acc0[j].z);
                acc0[j].w = fmaf(a4[j], b0.w, acc0[j].w);
                acc1[j].x = fmaf(a4[j], b1.x, acc1[j].x);
                acc1[j].y = fmaf(a4[j], b1.y, acc1[j].y);
                acc1[j].z = fmaf(a4[j], b1.z, acc1[j].z);
                acc1[j].w = fmaf(a4[j], b1.w, acc1[j].w);
            }
        }
        __syncthreads();
    }

    #pragma unroll
    for (int j = 0; j < 4; j++) {
        int gr = r0 + ty * 4 + j;
        if (gr < N_NODES) {
            *(float4*)(out + (size_t)gr * F_OUT + tx * 4)      = acc0[j];
            *(float4*)(out + (size_t)gr * F_OUT + tx * 4 + 32) = acc1[j];
            __half2* hp = (__half2*)(outh + (size_t)gr * F_OUT);
            hp[tx * 2]      = __floats2half2_rn(acc0[j].x, acc0[j].y);
            hp[tx * 2 + 1]  = __floats2half2_rn(acc0[j].z, acc0[j].w);
            hp[tx * 2 + 16] = __floats2half2_rn(acc1[j].x, acc1[j].y);
            hp[tx * 2 + 17] = __floats2half2_rn(acc1[j].z, acc1[j].w);
        }
    }
}

// ---------------------------------------------------------------------------
// CSR build (fused across 4 operators via blockIdx.y) — champion (2 edges/thr)
// ---------------------------------------------------------------------------
__global__ void hist_rank(const int* __restrict__ i0, const int* __restrict__ i1,
                          const int* __restrict__ i2, const int* __restrict__ i3,
                          int* __restrict__ cnt, unsigned* __restrict__ rank)
{
    const int op = blockIdx.y;
    const int* idx = (op == 0) ? i0 : (op == 1) ? i1 : (op == 2) ? i2 : i3;
    int e = (blockIdx.x * blockDim.x + threadIdx.x) * 2;
    if (e + 1 < N_EDGES) {
        int2 rr = *(const int2*)(idx + e);
        unsigned k0 = atomicAdd(&cnt[op * N_NODES + rr.x], 1);
        unsigned k1 = atomicAdd(&cnt[op * N_NODES + rr.y], 1);
        uint2 pk = make_uint2(((unsigned)rr.x << 15) | k0,
                              ((unsigned)rr.y << 15) | k1);
        *(uint2*)(rank + (size_t)op * N_EDGES + e) = pk;
    }
}

__global__ void scan_blocks(const int* __restrict__ cnt, int* __restrict__ excl,
                            int* __restrict__ bsum)
{
    __shared__ int sh[256];
    const int op = blockIdx.y;
    const int t = threadIdx.x;
    const int base = blockIdx.x * SCAN_BLK + t * 4;
    const int* c = cnt + op * N_NODES;
    int* ex = excl + op * (N_NODES + 1);

    int v[4];
    #pragma unroll
    for (int i = 0; i < 4; i++)
        v[i] = (base + i < N_NODES) ? c[base + i] : 0;
    int s = v[0] + v[1] + v[2] + v[3];
    sh[t] = s;
    __syncthreads();
    #pragma unroll
    for (int off = 1; off < 256; off <<= 1) {
        int x = (t >= off) ? sh[t - off] : 0;
        __syncthreads();
        sh[t] += x;
        __syncthreads();
    }
    int run = sh[t] - s;
    #pragma unroll
    for (int i = 0; i < 4; i++) {
        if (base + i < N_NODES) ex[base + i] = run;
        run += v[i];
    }
    if (t == 255) bsum[op * (NB_SCAN + 1) + blockIdx.x] = sh[255];
}

__global__ void scan_bsums(const int* __restrict__ bsum, int* __restrict__ bsumx)
{
    const int op   = threadIdx.x >> 5;
    const int lane = threadIdx.x & 31;
    const int* b = bsum  + op * (NB_SCAN + 1);
    int*      bx = bsumx + op * (NB_SCAN + 1);
    int carry = 0;
    #pragma unroll
    for (int c = 0; c < (NB_SCAN + 31) / 32; c++) {
        int i = c * 32 + lane;
        int v = (i < NB_SCAN) ? b[i] : 0;
        int s = v;
        #pragma unroll
        for (int off = 1; off < 32; off <<= 1) {
            int t = __shfl_up_sync(0xffffffffu, s, off);
            if (lane >= off) s += t;
        }
        if (i < NB_SCAN) bx[i] = carry + s - v;
        carry += __shfl_sync(0xffffffffu, s, 31);
    }
}

__global__ void scan_addback(const int* __restrict__ bsumx, int* __restrict__ rowptr)
{
    const int op = blockIdx.y;
    int i = blockIdx.x * blockDim.x + threadIdx.x;
    int* rp = rowptr + op * (N_NODES + 1);
    if (i < N_NODES)
        rp[i] += bsumx[op * (NB_SCAN + 1) + (i >> 10)];
    if (i == N_NODES) rp[N_NODES] = N_EDGES;
}

__global__ void scatter_edges(const int* __restrict__ i0, const int* __restrict__ i1,
                              const int* __restrict__ i2, const int* __restrict__ i3,
                              const float* __restrict__ v0, const float* __restrict__ v1,
                              const float* __restrict__ v2, const float* __restrict__ v3,
                              const int* __restrict__ rowptr,
                              const unsigned* __restrict__ rank,
                              int2* __restrict__ out)
{
    const int op = blockIdx.y;
    const int*   idx = (op == 0) ? i0 : (op == 1) ? i1 : (op == 2) ? i2 : i3;
    const float* val = (op == 0) ? v0 : (op == 1) ? v1 : (op == 2) ? v2 : v3;
    int e = (blockIdx.x * blockDim.x + threadIdx.x) * 2;
    if (e + 1 < N_EDGES) {
        int2   cc = *(const int2*)(idx + N_EDGES + e);     // source cols
        float2 vv = *(const float2*)(val + e);
        uint2  pk = *(const uint2*)(rank + (size_t)op * N_EDGES + e);
        const int* rp = rowptr + op * (N_NODES + 1);
        int pos0 = rp[pk.x >> 15] + (int)(pk.x & 0x7fffu);
        int pos1 = rp[pk.y >> 15] + (int)(pk.y & 0x7fffu);
        int2* ob = out + (size_t)op * N_EDGES;
        ob[pos0] = make_int2(cc.x, __float_as_int(vv.x));
        ob[pos1] = make_int2(cc.y, __float_as_int(vv.y));
    }
}

// ---------------------------------------------------------------------------
// CSR SPMM core: smem-broadcast edge staging (double-buffered, 1 syncwarp
// per 32-edge batch) replaces the 2-SHFL/edge distribution. Gather pattern
// unchanged (full-warp coalesced half2). fp32 accumulate, fp16 output.
// ---------------------------------------------------------------------------
__device__ __forceinline__ void spmm_row_h(const int* __restrict__ rowptr,
                                           const int2* __restrict__ eg,
                                           const __half* __restrict__ in,
                                           __half* __restrict__ out,
                                           int warp, int lane, int2* sbuf)
{
    const int s = rowptr[warp];
    const int e = rowptr[warp + 1];
    float ax = 0.f, ay = 0.f;

    int p = 0;
    for (int b = s; b < e; b += 32, p ^= 1) {
        const int m = min(32, e - b);
        if (lane < m) sbuf[p * 32 + lane] = eg[b + lane];
        __syncwarp();
        const int2* cur = sbuf + p * 32;

        int j = 0;
        for (; j + 4 <= m; j += 4) {
            int2 e0 = cur[j];
            int2 e1 = cur[j + 1];
            int2 e2 = cur[j + 2];
            int2 e3 = cur[j + 3];
            float2 x0 = __half22float2(*((const __half2*)(in + (size_t)e0.x * F_OUT) + lane));
            float2 x1 = __half22float2(*((const __half2*)(in + (size_t)e1.x * F_OUT) + lane));
            float2 x2 = __half22float2(*((const __half2*)(in + (size_t)e2.x * F_OUT) + lane));
            float2 x3 = __half22float2(*((const __half2*)(in + (size_t)e3.x * F_OUT) + lane));
            float v0 = __int_as_float(e0.y), v1 = __int_as_float(e1.y);
            float v2 = __int_as_float(e2.y), v3 = __int_as_float(e3.y);
            ax = fmaf(v0, x0.x, ax); ay = fmaf(v0, x0.y, ay);
            ax = fmaf(v1, x1.x, ax); ay = fmaf(v1, x1.y, ay);
            ax = fmaf(v2, x2.x, ax); ay = fmaf(v2, x2.y, ay);
            ax = fmaf(v3, x3.x, ax); ay = fmaf(v3, x3.y, ay);
        }
        for (; j < m; j++) {
            int2 ed = cur[j];
            float v = __int_as_float(ed.y);
            float2 xv = __half22float2(*((const __half2*)(in + (size_t)ed.x * F_OUT) + lane));
            ax = fmaf(v, xv.x, ax); ay = fmaf(v, xv.y, ay);
        }
    }

    *((__half2*)(out + (size_t)warp * F_OUT) + lane) = __floats2half2_rn(ax, ay);
}

// Fused launch: y=0 -> A·s0 (channel 0), y=1..3 -> P1..P3 (channels 3..5).
__global__ void spmm_fused4(const int* __restrict__ rowptr_all,
                            const int2* __restrict__ eg_all,
                            const __half* __restrict__ s0h,
                            __half* __restrict__ acch)
{
    __shared__ int2 sed[8][64];                      // 8 warps x double buffer
    const int op = blockIdx.y;                       // 0..3
    const int wid  = threadIdx.x >> 5;
    const int warp = (blockIdx.x * blockDim.x + threadIdx.x) >> 5;
    const int lane = threadIdx.x & 31;
    if (warp >= N_NODES) return;

    const int*  rowptr = rowptr_all + op * (N_NODES + 1);
    const int2* eg     = eg_all + (size_t)op * N_EDGES;
    __half* out = acch + (size_t)((op == 0) ? 0 : op + 2) * NF;
    spmm_row_h(rowptr, eg, s0h, out, warp, lane, sed[wid]);
}

// Single chain hop: gather fp16 'in', write fp16 'out'.
__global__ void spmm_hop(const int* __restrict__ rowptr, const int2* __restrict__ eg,
                         const __half* __restrict__ in, __half* __restrict__ out)
{
    __shared__ int2 sed[8][64];
    const int wid  = threadIdx.x >> 5;
    const int warp = (blockIdx.x * blockDim.x + threadIdx.x) >> 5;
    const int lane = threadIdx.x & 31;
    if (warp >= N_NODES) return;
    spmm_row_h(rowptr, eg, in, out, warp, lane, sed[wid]);
}

// ---------------------------------------------------------------------------
// Finalize (channels read fp16)
// ---------------------------------------------------------------------------
__global__ void finalize(const float* __restrict__ s0, const float* __restrict__ a,
                         float* __restrict__ out_hp, float* __restrict__ out_att)
{
    __shared__ float ch[8][6][64];
    __shared__ float as[768];

    const int tid = threadIdx.x;
    for (int i = tid; i < 768; i += 256) as[i] = a[i];

    const int w    = tid >> 5;
    const int lane = tid & 31;
    const int r    = blockIdx.x * 8 + w;
    __syncthreads();

    #pragma unroll
    for (int c = 0; c < 6; c++) {
        float2 v = __half22float2(*((const __half2*)(g_acch[c]) + (size_t)r * 32 + lane));
        if (c >= 3) { v.x = fabsf(v.x); v.y = fabsf(v.y); }
        ch[w][c][2 * lane]     = v.x;
        ch[w][c][2 * lane + 1] = v.y;
    }
    __syncwarp();

    float p[6];
    if (r < N_NODES / 2) {
        size_t b0 = (size_t)(2 * r) * F_OUT;
        size_t b1 = (size_t)(2 * r + 1) * F_OUT;
        float2 u = *(const float2*)(s0 + b0 + 2 * lane);
        float2 t = *(const float2*)(s0 + b1 + 2 * lane);
        #pragma unroll
        for (int i = 0; i < 6; i++) {
            const float* ai = as + i * 128;
            p[i] = ai[2 * lane] * u.x + ai[2 * lane + 1] * u.y
                 + ai[64 + 2 * lane] * t.x + ai[64 + 2 * lane + 1] * t.y;
        }
    } else {
        int q = 2 * r - N_NODES;
        #pragma unroll
        for (int i = 0; i < 6; i++) {
            float2 u = __half22float2(*((const __half2*)(g_acch[i]) + (size_t)q * 32 + lane));
            float2 t = __half22float2(*((const __half2*)(g_acch[i]) + (size_t)(q + 1) * 32 + lane));
            if (i >= 3) { u.x = fabsf(u.x); u.y = fabsf(u.y); t.x = fabsf(t.x); t.y = fabsf(t.y); }
            const float* ai = as + i * 128;
            p[i] = ai[2 * lane] * u.x + ai[2 * lane + 1] * u.y
                 + ai[64 + 2 * lane] * t.x + ai[64 + 2 * lane + 1] * t.y;
        }
    }

    #pragma unroll
    for (int i = 0; i < 6; i++) {
        #pragma unroll
        for (int off = 16; off; off >>= 1)
            p[i] += __shfl_down_sync(0xffffffffu, p[i], off);
        p[i] = __shfl_sync(0xffffffffu, p[i], 0);
    }

    float m = p[0];
    #pragma unroll
    for (int i = 1; i < 6; i++) m = fmaxf(m, p[i]);
    float att[6], s = 0.f;
    #pragma unroll
    for (int i = 0; i < 6; i++) { att[i] = expf(p[i] - m); s += att[i]; }
    float inv = 1.f / s;
    #pragma unroll
    for (int i = 0; i < 6; i++) att[i] *= inv;

    if (out_att && lane == 0) {
        #pragma unroll
        for (int i = 0; i < 6; i++) out_att[(size_t)r * 6 + i] = att[i];
    }

    #pragma unroll
    for (int kk = 0; kk < 2; kk++) {
        int k = lane + kk * 32;
        float hp = 0.f;
        #pragma unroll
        for (int j = 0; j < 6; j++) {
            int idx = j * 64 + k;
            hp = fmaf(att[j], ch[w][idx % 6][idx / 6], hp);
        }
        out_hp[(size_t)r * F_OUT + k] = hp * (1.0f / 6.0f);
    }
}

// ---------------------------------------------------------------------------
extern "C" void kernel_launch(void* const* d_in, const int* in_sizes, int n_in,
                              void* d_out, int out_size)
{
    const float* x  = (const float*)d_in[0];
    const float* W  = (const float*)d_in[1];
    const float* a  = (const float*)d_in[2];
    const int*   iA  = (const int*)d_in[3];   const float* vA  = (const float*)d_in[4];
    const int*   iP1 = (const int*)d_in[5];   const float* vP1 = (const float*)d_in[6];
    const int*   iP2 = (const int*)d_in[7];   const float* vP2 = (const float*)d_in[8];
    const int*   iP3 = (const int*)d_in[9];   const float* vP3 = (const float*)d_in[10];

    float*    s0;   cudaGetSymbolAddress((void**)&s0,   g_s0);
    __half*   s0h;  cudaGetSymbolAddress((void**)&s0h,  g_s0h);
    __half*   acch; cudaGetSymbolAddress((void**)&acch, g_acch);
    int*      cnt;  cudaGetSymbolAddress((void**)&cnt,  g_cnt);
    int*      rp;   cudaGetSymbolAddress((void**)&rp,   g_rowptr);
    unsigned* rk;   cudaGetSymbolAddress((void**)&rk,   g_rank);
    int2*     eg;   cudaGetSymbolAddress((void**)&eg,   g_edges);
    int*      bs;   cudaGetSymbolAddress((void**)&bs,   g_bsum);
    int*      bsx;  cudaGetSymbolAddress((void**)&bsx,  g_bsumx);

    // One-time host-side resources (no device memory).
    static cudaStream_t s_side = nullptr;
    static cudaEvent_t  ev_fork = nullptr, ev_join = nullptr;
    if (!s_side) {
        cudaStreamCreateWithFlags(&s_side, cudaStreamNonBlocking);
        cudaEventCreateWithFlags(&ev_fork, cudaEventDisableTiming);
        cudaEventCreateWithFlags(&ev_join, cudaEventDisableTiming);
    }

    // Fork: CSR build on side stream, GEMM on main stream (independent).
    cudaEventRecord(ev_fork, 0);
    cudaStreamWaitEvent(s_side, ev_fork, 0);

    gemm64<<<(N_NODES + 63) / 64, 128>>>(x, W, s0, s0h);

    cudaMemsetAsync(cnt, 0, sizeof(int) * 4 * N_NODES, s_side);
    const dim3 EG2((N_EDGES / 2 + 255) / 256, 4);
    hist_rank<<<EG2, 256, 0, s_side>>>(iA, iP1, iP2, iP3, cnt, rk);
    scan_blocks<<<dim3(NB_SCAN, 4), 256, 0, s_side>>>(cnt, rp, bs);
    scan_bsums<<<1, 128, 0, s_side>>>(bs, bsx);
    scan_addback<<<dim3((N_NODES + 256) / 256, 4), 256, 0, s_side>>>(bsx, rp);
    scatter_edges<<<EG2, 256, 0, s_side>>>(iA, iP1, iP2, iP3, vA, vP1, vP2, vP3,
                                           rp, rk, eg);

    cudaEventRecord(ev_join, s_side);
    cudaStreamWaitEvent(0, ev_join, 0);

    const int SG = (N_NODES * 32 + 255) / 256;
    // Fused: A·s0 -> ch0, P1..P3 -> ch3..5 (fp16 gather from s0h)
    spmm_fused4<<<dim3(SG, 4), 256>>>(rp, eg, s0h, acch);
    // Chain hops 2,3 (fp16 in/out)
    spmm_hop<<<SG, 256>>>(rp, eg, acch + 0 * (size_t)NF, acch + 1 * (size_t)NF);
    spmm_hop<<<SG, 256>>>(rp, eg, acch + 1 * (size_t)NF, acch + 2 * (size_t)NF);

    float* out = (float*)d_out;
    float* att = (out_size >= N_NODES * F_OUT + N_NODES * 6)
                     ? out + (size_t)N_NODES * F_OUT : nullptr;
    finalize<<<N_NODES / 8, 256>>>(s0, a, out, att);
}

// round 17
// speedup vs baseline: 1.1738x; 1.0111x over previous
#include <cuda_runtime.h>
#include <cuda_fp16.h>
#include <cstddef>

#define N_NODES 100000
#define N_EDGES 3200000
#define F_IN    256
#define F_OUT   64
#define NF      (N_NODES * F_OUT)
#define SCAN_BLK 1024
#define NB_SCAN  ((N_NODES + SCAN_BLK - 1) / SCAN_BLK)   // 98

// Scratch (device globals; allocation-free).
__device__ float    g_s0[NF];
__device__ __half   g_s0h[NF];            // fp16 s0 (gather source)
__device__ __half   g_acch[6][NF];        // fp16 channels: hA,hA2,hA3,hs1,hs2,hs3
__device__ int      g_cnt[4][N_NODES];
__device__ int      g_rowptr[4][N_NODES + 1];
__device__ unsigned g_rank[4][N_EDGES];   // packed (row<<15)|rank
__device__ int2     g_edges[4][N_EDGES];  // (col, val-as-int), dest-sorted
__device__ int      g_bsum[4][NB_SCAN + 1];
__device__ int      g_bsumx[4][NB_SCAN + 1];

// ---------------------------------------------------------------------------
// GEMM: s0[N,64] = x[N,256] @ W[256,64], fp32; also emits fp16 copy.
// ---------------------------------------------------------------------------
__global__ void gemm64(const float* __restrict__ x, const float* __restrict__ W,
                       float* __restrict__ out, __half* __restrict__ outh)
{
    __shared__ float xs[32][64];
    __shared__ float ws[32][64];

    const int tid = threadIdx.x;       // 0..127
    const int tx  = tid & 7;
    const int ty  = tid >> 3;
    const int r0  = blockIdx.x * 64;

    float4 acc0[4] = {};
    float4 acc1[4] = {};

    for (int k0 = 0; k0 < F_IN; k0 += 32) {
        #pragma unroll
        for (int it = 0; it < 4; it++) {
            int li  = it * 128 + tid;
            int row = li >> 3;
            int kq  = li & 7;
            float4 v = make_float4(0.f, 0.f, 0.f, 0.f);
            int gr = r0 + row;
            if (gr < N_NODES)
                v = *(const float4*)(x + (size_t)gr * F_IN + k0 + kq * 4);
            xs[kq * 4 + 0][row] = v.x;
            xs[kq * 4 + 1][row] = v.y;
            xs[kq * 4 + 2][row] = v.z;
            xs[kq * 4 + 3][row] = v.w;
        }
        #pragma unroll
        for (int it = 0; it < 4; it++) {
            int li = it * 128 + tid;
            int kk = li >> 4;
            int cq = li & 15;
            *(float4*)&ws[kk][cq * 4] =
                *(const float4*)(W + (size_t)(k0 + kk) * F_OUT + cq * 4);
        }
        __syncthreads();

        #pragma unroll
        for (int kk = 0; kk < 32; kk++) {
            float4 av = *(const float4*)&xs[kk][ty * 4];
            float4 b0 = *(const float4*)&ws[kk][tx * 4];
            float4 b1 = *(const float4*)&ws[kk][tx * 4 + 32];
            float a4[4] = {av.x, av.y, av.z, av.w};
            #pragma unroll
            for (int j = 0; j < 4; j++) {
                acc0[j].x = fmaf(a4[j], b0.x, acc0[j].x);
                acc0[j].y = fmaf(a4[j], b0.y, acc0[j].y);
                acc0[j].z = fmaf(a4[j], b0.z, acc0[j].z);
                acc0[j].w = fmaf(a4[j], b0.w, acc0[j].w);
                acc1[j].x = fmaf(a4[j], b1.x, acc1[j].x);
                acc1[j].y = fmaf(a4[j], b1.y, acc1[j].y);
                acc1[j].z = fmaf(a4[j], b1.z, acc1[j].z);
                acc1[j].w = fmaf(a4[j], b1.w, acc1[j].w);
            }
        }
        __syncthreads();
    }

    #pragma unroll
    for (int j = 0; j < 4; j++) {
        int gr = r0 + ty * 4 + j;
        if (gr < N_NODES) {
            *(float4*)(out + (size_t)gr * F_OUT + tx * 4)      = acc0[j];
            *(float4*)(out + (size_t)gr * F_OUT + tx * 4 + 32) = acc1[j];
            __half2* hp = (__half2*)(outh + (size_t)gr * F_OUT);
            hp[tx * 2]      = __floats2half2_rn(acc0[j].x, acc0[j].y);
            hp[tx * 2 + 1]  = __floats2half2_rn(acc0[j].z, acc0[j].w);
            hp[tx * 2 + 16] = __floats2half2_rn(acc1[j].x, acc1[j].y);
            hp[tx * 2 + 17] = __floats2half2_rn(acc1[j].z, acc1[j].w);
        }
    }
}

// ---------------------------------------------------------------------------
// CSR build (fused across 4 operators via blockIdx.y) — champion (2 edges/thr)
// ---------------------------------------------------------------------------
__global__ void hist_rank(const int* __restrict__ i0, const int* __restrict__ i1,
                          const int* __restrict__ i2, const int* __restrict__ i3,
                          int* __restrict__ cnt, unsigned* __restrict__ rank)
{
    const int op = blockIdx.y;
    const int* idx = (op == 0) ? i0 : (op == 1) ? i1 : (op == 2) ? i2 : i3;
    int e = (blockIdx.x * blockDim.x + threadIdx.x) * 2;
    if (e + 1 < N_EDGES) {
        int2 rr = *(const int2*)(idx + e);
        unsigned k0 = atomicAdd(&cnt[op * N_NODES + rr.x], 1);
        unsigned k1 = atomicAdd(&cnt[op * N_NODES + rr.y], 1);
        uint2 pk = make_uint2(((unsigned)rr.x << 15) | k0,
                              ((unsigned)rr.y << 15) | k1);
        *(uint2*)(rank + (size_t)op * N_EDGES + e) = pk;
    }
}

__global__ void scan_blocks(const int* __restrict__ cnt, int* __restrict__ excl,
                            int* __restrict__ bsum)
{
    __shared__ int sh[256];
    const int op = blockIdx.y;
    const int t = threadIdx.x;
    const int base = blockIdx.x * SCAN_BLK + t * 4;
    const int* c = cnt + op * N_NODES;
    int* ex = excl + op * (N_NODES + 1);

    int v[4];
    #pragma unroll
    for (int i = 0; i < 4; i++)
        v[i] = (base + i < N_NODES) ? c[base + i] : 0;
    int s = v[0] + v[1] + v[2] + v[3];
    sh[t] = s;
    __syncthreads();
    #pragma unroll
    for (int off = 1; off < 256; off <<= 1) {
        int x = (t >= off) ? sh[t - off] : 0;
        __syncthreads();
        sh[t] += x;
        __syncthreads();
    }
    int run = sh[t] - s;
    #pragma unroll
    for (int i = 0; i < 4; i++) {
        if (base + i < N_NODES) ex[base + i] = run;
        run += v[i];
    }
    if (t == 255) bsum[op * (NB_SCAN + 1) + blockIdx.x] = sh[255];
}

__global__ void scan_bsums(const int* __restrict__ bsum, int* __restrict__ bsumx)
{
    const int op   = threadIdx.x >> 5;
    const int lane = threadIdx.x & 31;
    const int* b = bsum  + op * (NB_SCAN + 1);
    int*      bx = bsumx + op * (NB_SCAN + 1);
    int carry = 0;
    #pragma unroll
    for (int c = 0; c < (NB_SCAN + 31) / 32; c++) {
        int i = c * 32 + lane;
        int v = (i < NB_SCAN) ? b[i] : 0;
        int s = v;
        #pragma unroll
        for (int off = 1; off < 32; off <<= 1) {
            int t = __shfl_up_sync(0xffffffffu, s, off);
            if (lane >= off) s += t;
        }
        if (i < NB_SCAN) bx[i] = carry + s - v;
        carry += __shfl_sync(0xffffffffu, s, 31);
    }
}

__global__ void scan_addback(const int* __restrict__ bsumx, int* __restrict__ rowptr)
{
    const int op = blockIdx.y;
    int i = blockIdx.x * blockDim.x + threadIdx.x;
    int* rp = rowptr + op * (N_NODES + 1);
    if (i < N_NODES)
        rp[i] += bsumx[op * (NB_SCAN + 1) + (i >> 10)];
    if (i == N_NODES) rp[N_NODES] = N_EDGES;
}

__global__ void scatter_edges(const int* __restrict__ i0, const int* __restrict__ i1,
                              const int* __restrict__ i2, const int* __restrict__ i3,
                              const float* __restrict__ v0, const float* __restrict__ v1,
                              const float* __restrict__ v2, const float* __restrict__ v3,
                              const int* __restrict__ rowptr,
                              const unsigned* __restrict__ rank,
                              int2* __restrict__ out)
{
    const int op = blockIdx.y;
    const int*   idx = (op == 0) ? i0 : (op == 1) ? i1 : (op == 2) ? i2 : i3;
    const float* val = (op == 0) ? v0 : (op == 1) ? v1 : (op == 2) ? v2 : v3;
    int e = (blockIdx.x * blockDim.x + threadIdx.x) * 2;
    if (e + 1 < N_EDGES) {
        int2   cc = *(const int2*)(idx + N_EDGES + e);     // source cols
        float2 vv = *(const float2*)(val + e);
        uint2  pk = *(const uint2*)(rank + (size_t)op * N_EDGES + e);
        const int* rp = rowptr + op * (N_NODES + 1);
        int pos0 = rp[pk.x >> 15] + (int)(pk.x & 0x7fffu);
        int pos1 = rp[pk.y >> 15] + (int)(pk.y & 0x7fffu);
        int2* ob = out + (size_t)op * N_EDGES;
        ob[pos0] = make_int2(cc.x, __float_as_int(vv.x));
        ob[pos1] = make_int2(cc.y, __float_as_int(vv.y));
    }
}

// ---------------------------------------------------------------------------
// CSR SPMM core: smem-broadcast edge staging (double-buffered, 1 syncwarp
// per 32-edge batch); metadata fetched 2 edges at a time via broadcast
// LDS.128 (int4 = edges j, j+1). Gather pattern unchanged. fp32 accumulate,
// fp16 output.
// ---------------------------------------------------------------------------
__device__ __forceinline__ void spmm_row_h(const int* __restrict__ rowptr,
                                           const int2* __restrict__ eg,
                                           const __half* __restrict__ in,
                                           __half* __restrict__ out,
                                           int warp, int lane, int2* sbuf)
{
    const int s = rowptr[warp];
    const int e = rowptr[warp + 1];
    float ax = 0.f, ay = 0.f;

    int p = 0;
    for (int b = s; b < e; b += 32, p ^= 1) {
        const int m = min(32, e - b);
        if (lane < m) sbuf[p * 32 + lane] = eg[b + lane];
        __syncwarp();
        const int4* cur4 = (const int4*)(sbuf + p * 32);   // 2 edges per int4

        int j = 0;
        for (; j + 4 <= m; j += 4) {
            int4 ea = cur4[(j >> 1)];        // edges j, j+1
            int4 eb = cur4[(j >> 1) + 1];    // edges j+2, j+3
            float2 x0 = __half22float2(*((const __half2*)(in + (size_t)ea.x * F_OUT) + lane));
            float2 x1 = __half22float2(*((const __half2*)(in + (size_t)ea.z * F_OUT) + lane));
            float2 x2 = __half22float2(*((const __half2*)(in + (size_t)eb.x * F_OUT) + lane));
            float2 x3 = __half22float2(*((const __half2*)(in + (size_t)eb.z * F_OUT) + lane));
            float v0 = __int_as_float(ea.y), v1 = __int_as_float(ea.w);
            float v2 = __int_as_float(eb.y), v3 = __int_as_float(eb.w);
            ax = fmaf(v0, x0.x, ax); ay = fmaf(v0, x0.y, ay);
            ax = fmaf(v1, x1.x, ax); ay = fmaf(v1, x1.y, ay);
            ax = fmaf(v2, x2.x, ax); ay = fmaf(v2, x2.y, ay);
            ax = fmaf(v3, x3.x, ax); ay = fmaf(v3, x3.y, ay);
        }
        const int2* cur = sbuf + p * 32;
        for (; j < m; j++) {
            int2 ed = cur[j];
            float v = __int_as_float(ed.y);
            float2 xv = __half22float2(*((const __half2*)(in + (size_t)ed.x * F_OUT) + lane));
            ax = fmaf(v, xv.x, ax); ay = fmaf(v, xv.y, ay);
        }
    }

    *((__half2*)(out + (size_t)warp * F_OUT) + lane) = __floats2half2_rn(ax, ay);
}

// Fused launch: y=0 -> A·s0 (channel 0), y=1..3 -> P1..P3 (channels 3..5).
__global__ void spmm_fused4(const int* __restrict__ rowptr_all,
                            const int2* __restrict__ eg_all,
                            const __half* __restrict__ s0h,
                            __half* __restrict__ acch)
{
    __shared__ __align__(16) int2 sed[8][64];        // 8 warps x double buffer
    const int op = blockIdx.y;                       // 0..3
    const int wid  = threadIdx.x >> 5;
    const int warp = (blockIdx.x * blockDim.x + threadIdx.x) >> 5;
    const int lane = threadIdx.x & 31;
    if (warp >= N_NODES) return;

    const int*  rowptr = rowptr_all + op * (N_NODES + 1);
    const int2* eg     = eg_all + (size_t)op * N_EDGES;
    __half* out = acch + (size_t)((op == 0) ? 0 : op + 2) * NF;
    spmm_row_h(rowptr, eg, s0h, out, warp, lane, sed[wid]);
}

// Single chain hop: gather fp16 'in', write fp16 'out'.
__global__ void spmm_hop(const int* __restrict__ rowptr, const int2* __restrict__ eg,
                         const __half* __restrict__ in, __half* __restrict__ out)
{
    __shared__ __align__(16) int2 sed[8][64];
    const int wid  = threadIdx.x >> 5;
    const int warp = (blockIdx.x * blockDim.x + threadIdx.x) >> 5;
    const int lane = threadIdx.x & 31;
    if (warp >= N_NODES) return;
    spmm_row_h(rowptr, eg, in, out, warp, lane, sed[wid]);
}

// ---------------------------------------------------------------------------
// Finalize (channels read fp16)
// ---------------------------------------------------------------------------
__global__ void finalize(const float* __restrict__ s0, const float* __restrict__ a,
                         float* __restrict__ out_hp, float* __restrict__ out_att)
{
    __shared__ float ch[8][6][64];
    __shared__ float as[768];

    const int tid = threadIdx.x;
    for (int i = tid; i < 768; i += 256) as[i] = a[i];

    const int w    = tid >> 5;
    const int lane = tid & 31;
    const int r    = blockIdx.x * 8 + w;
    __syncthreads();

    #pragma unroll
    for (int c = 0; c < 6; c++) {
        float2 v = __half22float2(*((const __half2*)(g_acch[c]) + (size_t)r * 32 + lane));
        if (c >= 3) { v.x = fabsf(v.x); v.y = fabsf(v.y); }
        ch[w][c][2 * lane]     = v.x;
        ch[w][c][2 * lane + 1] = v.y;
    }
    __syncwarp();

    float p[6];
    if (r < N_NODES / 2) {
        size_t b0 = (size_t)(2 * r) * F_OUT;
        size_t b1 = (size_t)(2 * r + 1) * F_OUT;
        float2 u = *(const float2*)(s0 + b0 + 2 * lane);
        float2 t = *(const float2*)(s0 + b1 + 2 * lane);
        #pragma unroll
        for (int i = 0; i < 6; i++) {
            const float* ai = as + i * 128;
            p[i] = ai[2 * lane] * u.x + ai[2 * lane + 1] * u.y
                 + ai[64 + 2 * lane] * t.x + ai[64 + 2 * lane + 1] * t.y;
        }
    } else {
        int q = 2 * r - N_NODES;
        #pragma unroll
        for (int i = 0; i < 6; i++) {
            float2 u = __half22float2(*((const __half2*)(g_acch[i]) + (size_t)q * 32 + lane));
            float2 t = __half22float2(*((const __half2*)(g_acch[i]) + (size_t)(q + 1) * 32 + lane));
            if (i >= 3) { u.x = fabsf(u.x); u.y = fabsf(u.y); t.x = fabsf(t.x); t.y = fabsf(t.y); }
            const float* ai = as + i * 128;
            p[i] = ai[2 * lane] * u.x + ai[2 * lane + 1] * u.y
                 + ai[64 + 2 * lane] * t.x + ai[64 + 2 * lane + 1] * t.y;
        }
    }

    #pragma unroll
    for (int i = 0; i < 6; i++) {
        #pragma unroll
        for (int off = 16; off; off >>= 1)
            p[i] += __shfl_down_sync(0xffffffffu, p[i], off);
        p[i] = __shfl_sync(0xffffffffu, p[i], 0);
    }

    float m = p[0];
    #pragma unroll
    for (int i = 1; i < 6; i++) m = fmaxf(m, p[i]);
    float att[6], s = 0.f;
    #pragma unroll
    for (int i = 0; i < 6; i++) { att[i] = expf(p[i] - m); s += att[i]; }
    float inv = 1.f / s;
    #pragma unroll
    for (int i = 0; i < 6; i++) att[i] *= inv;

    if (out_att && lane == 0) {
        #pragma unroll
        for (int i = 0; i < 6; i++) out_att[(size_t)r * 6 + i] = att[i];
    }

    #pragma unroll
    for (int kk = 0; kk < 2; kk++) {
        int k = lane + kk * 32;
        float hp = 0.f;
        #pragma unroll
        for (int j = 0; j < 6; j++) {
            int idx = j * 64 + k;
            hp = fmaf(att[j], ch[w][idx % 6][idx / 6], hp);
        }
        out_hp[(size_t)r * F_OUT + k] = hp * (1.0f / 6.0f);
    }
}

// ---------------------------------------------------------------------------
extern "C" void kernel_launch(void* const* d_in, const int* in_sizes, int n_in,
                              void* d_out, int out_size)
{
    const float* x  = (const float*)d_in[0];
    const float* W  = (const float*)d_in[1];
    const float* a  = (const float*)d_in[2];
    const int*   iA  = (const int*)d_in[3];   const float* vA  = (const float*)d_in[4];
    const int*   iP1 = (const int*)d_in[5];   const float* vP1 = (const float*)d_in[6];
    const int*   iP2 = (const int*)d_in[7];   const float* vP2 = (const float*)d_in[8];
    const int*   iP3 = (const int*)d_in[9];   const float* vP3 = (const float*)d_in[10];

    float*    s0;   cudaGetSymbolAddress((void**)&s0,   g_s0);
    __half*   s0h;  cudaGetSymbolAddress((void**)&s0h,  g_s0h);
    __half*   acch; cudaGetSymbolAddress((void**)&acch, g_acch);
    int*      cnt;  cudaGetSymbolAddress((void**)&cnt,  g_cnt);
    int*      rp;   cudaGetSymbolAddress((void**)&rp,   g_rowptr);
    unsigned* rk;   cudaGetSymbolAddress((void**)&rk,   g_rank);
    int2*     eg;   cudaGetSymbolAddress((void**)&eg,   g_edges);
    int*      bs;   cudaGetSymbolAddress((void**)&bs,   g_bsum);
    int*      bsx;  cudaGetSymbolAddress((void**)&bsx,  g_bsumx);

    // One-time host-side resources (no device memory).
    static cudaStream_t s_side = nullptr;
    static cudaEvent_t  ev_fork = nullptr, ev_join = nullptr;
    if (!s_side) {
        cudaStreamCreateWithFlags(&s_side, cudaStreamNonBlocking);
        cudaEventCreateWithFlags(&ev_fork, cudaEventDisableTiming);
        cudaEventCreateWithFlags(&ev_join, cudaEventDisableTiming);
    }

    // Fork: CSR build on side stream, GEMM on main stream (independent).
    cudaEventRecord(ev_fork, 0);
    cudaStreamWaitEvent(s_side, ev_fork, 0);

    gemm64<<<(N_NODES + 63) / 64, 128>>>(x, W, s0, s0h);

    cudaMemsetAsync(cnt, 0, sizeof(int) * 4 * N_NODES, s_side);
    const dim3 EG2((N_EDGES / 2 + 255) / 256, 4);
    hist_rank<<<EG2, 256, 0, s_side>>>(iA, iP1, iP2, iP3, cnt, rk);
    scan_blocks<<<dim3(NB_SCAN, 4), 256, 0, s_side>>>(cnt, rp, bs);
    scan_bsums<<<1, 128, 0, s_side>>>(bs, bsx);
    scan_addback<<<dim3((N_NODES + 256) / 256, 4), 256, 0, s_side>>>(bsx, rp);
    scatter_edges<<<EG2, 256, 0, s_side>>>(iA, iP1, iP2, iP3, vA, vP1, vP2, vP3,
                                           rp, rk, eg);

    cudaEventRecord(ev_join, s_side);
    cudaStreamWaitEvent(0, ev_join, 0);

    const int SG = (N_NODES * 32 + 255) / 256;
    // Fused: A·s0 -> ch0, P1..P3 -> ch3..5 (fp16 gather from s0h)
    spmm_fused4<<<dim3(SG, 4), 256>>>(rp, eg, s0h, acch);
    // Chain hops 2,3 (fp16 in/out)
    spmm_hop<<<SG, 256>>>(rp, eg, acch + 0 * (size_t)NF, acch + 1 * (size_t)NF);
    spmm_hop<<<SG, 256>>>(rp, eg, acch + 1 * (size_t)NF, acch + 2 * (size_t)NF);

    float* out = (float*)d_out;
    float* att = (out_size >= N_NODES * F_OUT + N_NODES * 6)
                     ? out + (size_t)N_NODES * F_OUT : nullptr;
    finalize<<<N_NODES / 8, 256>>>(s0, a, out, att);
}